// round 14
// baseline (speedup 1.0000x reference)
#include <cuda_runtime.h>
#include <cuda_fp16.h>
#include <cstdint>

#define TILE 128
#define NT   256

// smem byte offsets. All fp16 tiles: rows of 128 B, SW128 swizzle.
#define S_BH    0        // GEMM1 B hi (k-cols permuted)            8 KB
#define S_BL    8192     // GEMM1 B lo*2048 (k-cols permuted)       8 KB
#define S_RT    16384    // GEMM2 B = R^T hi (n-rows permuted)      8 KB
#define S_XH    24576    // xn hi   [128][64] (cols permuted)      16 KB
#define S_XL    40960    // xn lo*2048 [128][64] (cols permuted)   16 KB
#define S_CB    57344    // float[16]
#define S_BND   57408    // float[15] + pad
#define S_SCALE 57472    // float[128]
#define SMEM_BYTES 57984

#define INV2048 4.8828125e-4f

static __device__ __forceinline__ uint32_t smem_u32(const void* p) {
    uint32_t a;
    asm("{ .reg .u64 t; cvta.to.shared.u64 t, %1; cvt.u32.u64 %0, t; }" : "=r"(a) : "l"(p));
    return a;
}
// byte offset of fp16 element (row, pos) in a [*][64] tile, SW128 swizzle
static __device__ __forceinline__ int sw(int row, int pos) {
    return row * 128 + ((pos * 2) ^ ((row & 7) << 4));
}
// fragment k-permutation: content k lives at tile position P(k)
static __device__ __forceinline__ int pperm(int s) {
    return ((s >> 2) << 1) | (s & 1) | ((s & 2) << 2);
}
static __device__ __forceinline__ uint32_t h2u(__half2 h) {
    return *reinterpret_cast<uint32_t*>(&h);
}
static __device__ __forceinline__ void ldsm4(uint32_t* r, uint32_t addr) {
    asm volatile("ldmatrix.sync.aligned.m8n8.x4.shared.b16 {%0,%1,%2,%3}, [%4];"
        : "=r"(r[0]), "=r"(r[1]), "=r"(r[2]), "=r"(r[3]) : "r"(addr));
}
static __device__ __forceinline__ void mma16816(float* c, const uint32_t* a,
                                                uint32_t b0, uint32_t b1) {
    asm volatile("mma.sync.aligned.m16n8k16.row.col.f32.f16.f16.f32 "
        "{%0,%1,%2,%3}, {%4,%5,%6,%7}, {%8,%9}, {%0,%1,%2,%3};"
        : "+f"(c[0]), "+f"(c[1]), "+f"(c[2]), "+f"(c[3])
        : "r"(a[0]), "r"(a[1]), "r"(a[2]), "r"(a[3]), "r"(b0), "r"(b1));
}

__global__ void __launch_bounds__(NT, 3)
tq_mma_kernel(const float* __restrict__ x, const float* __restrict__ cb,
              const float* __restrict__ Rg, float* __restrict__ out, int nrows)
{
    extern __shared__ char smem[];
    const uint32_t sb = smem_u32(smem);
    float* sCb    = (float*)(smem + S_CB);
    float* sBnd   = (float*)(smem + S_BND);
    float* sScale = (float*)(smem + S_SCALE);

    const int t   = threadIdx.x;
    const int wid = t >> 5;
    const int l   = t & 31;
    const int g   = l >> 2;
    const int tq  = l & 3;
    const long long row0 = (long long)blockIdx.x * TILE;

    // ---- stage R (half2 pairs; fragment k-permutation baked in) ----
    #pragma unroll 4
    for (int i = t; i < 2048; i += NT) {
        int j = i >> 5, kp = i & 31;
        int k = 2 * kp;
        float2 vv = *(const float2*)(Rg + j * 64 + k);
        __half2 hv = __floats2half2_rn(vv.x, vv.y);
        float2 hf = __half22float2(hv);
        __half2 lv = __floats2half2_rn((vv.x - hf.x) * 2048.0f, (vv.y - hf.y) * 2048.0f);
        int kk = (k & ~15) | pperm(k & 15);   // even; pair stays adjacent
        *(__half2*)(smem + S_BH + sw(j, kk)) = hv;
        *(__half2*)(smem + S_BL + sw(j, kk)) = lv;
        *(__half*)(smem + S_RT + sw(kk,     j)) = __low2half(hv);
        *(__half*)(smem + S_RT + sw(kk + 1, j)) = __high2half(hv);
    }
    if (t < 16) sCb[t] = cb[t];
    if (t < 15) sBnd[t] = 0.5f * (cb[t] + cb[t + 1]);

    // ---- prologue: 2 threads/row, coalesced float4 loads, norm, hi/lo tiles ----
    {
        int r = t >> 1, h = t & 1;
        long long grow = row0 + r;
        long long gr = grow < nrows ? grow : (long long)nrows - 1;
        const float4* xp = (const float4*)(x + gr * 64 + h * 32);
        float4 v[8];
        float ss = 0.f;
        #pragma unroll
        for (int i = 0; i < 8; i++) {
            v[i] = xp[i];
            ss += v[i].x*v[i].x + v[i].y*v[i].y + v[i].z*v[i].z + v[i].w*v[i].w;
        }
        ss += __shfl_xor_sync(0xffffffffu, ss, 1);
        float scale = fmaxf(sqrtf(ss), 1e-8f);
        float inv = 1.0f / scale;
        if (h == 0) sScale[r] = scale;
        #pragma unroll
        for (int i = 0; i < 8; i++) {
            int k0 = h * 32 + 4 * i;
            int base = k0 & ~15;
            int m = i & 3;
            int pA = base + 2 * m;      // positions of contents (k0, k0+1)
            int pB = pA + 8;            // positions of contents (k0+2, k0+3)
            float a0 = v[i].x * inv, a1 = v[i].y * inv;
            float a2 = v[i].z * inv, a3 = v[i].w * inv;
            __half2 hA = __floats2half2_rn(a0, a1);
            __half2 hB = __floats2half2_rn(a2, a3);
            float2 fA = __half22float2(hA), fB = __half22float2(hB);
            __half2 lA = __floats2half2_rn((a0 - fA.x) * 2048.0f, (a1 - fA.y) * 2048.0f);
            __half2 lB = __floats2half2_rn((a2 - fB.x) * 2048.0f, (a3 - fB.y) * 2048.0f);
            *(__half2*)(smem + S_XH + sw(r, pA)) = hA;
            *(__half2*)(smem + S_XH + sw(r, pB)) = hB;
            *(__half2*)(smem + S_XL + sw(r, pA)) = lA;
            *(__half2*)(smem + S_XL + sw(r, pB)) = lB;
        }
    }
    __syncthreads();

    // quantizer tables: tree levels 1-3 in regs, level 4 + values via warp shuffle
    const float m1 = sBnd[1], m3 = sBnd[3], m5 = sBnd[5], m7 = sBnd[7];
    const float m9 = sBnd[9], m11 = sBnd[11], m13 = sBnd[13];
    const float bndv = sBnd[l & 15];
    const float cbv  = sCb[l & 15];

    // ---- LDSM lane addressing ----
    // B tiles (n rows, k-pos cols)
    const int tl  = l >> 3;
    const int rwi = l & 7;
    const int rsel = ((tl & 2) << 2) + rwi;
    const int cbyte = (tl & 1) << 4;
    const int bswz = rwi << 4;
    int lo[4];
    #pragma unroll
    for (int ch = 0; ch < 4; ch++) lo[ch] = rsel * 128 + ((ch * 32 + cbyte) ^ bswz);
    // A tiles (row = wid*16 + (l&15), k-pos block 16ch + 8*(l>=16))
    const int arow = wid * 16 + (l & 15);
    const int adlt = ((l >> 4) & 1) << 4;   // byte offset of +8 positions
    const int aswz = (l & 7) << 4;
    const uint32_t abase = sb + (uint32_t)(arow * 128);
    int ao[4];
    #pragma unroll
    for (int ch = 0; ch < 4; ch++) ao[ch] = (ch * 32 + adlt) ^ aswz;

    // hoist A-hi fragments (16 regs)
    uint32_t ah[4][4];
    #pragma unroll
    for (int ch = 0; ch < 4; ch++) ldsm4(ah[ch], abase + S_XH + ao[ch]);

    // ==== PHASE 1: GEMM1 + quantize; E fragments in registers ====
    uint32_t aeAll[4][4];
    #pragma unroll
    for (int ntp = 0; ntp < 4; ntp++) {
        float c1[2][4], c2[2][4];
        #pragma unroll
        for (int s = 0; s < 2; s++)
            #pragma unroll
            for (int i = 0; i < 4; i++) { c1[s][i] = 0.f; c2[s][i] = 0.f; }

        #pragma unroll
        for (int ch = 0; ch < 4; ch++) {
            uint32_t bh[4], bl[4], al[4];
            ldsm4(bh, sb + S_BH + ntp * 2048 + lo[ch]);
            ldsm4(bl, sb + S_BL + ntp * 2048 + lo[ch]);
            ldsm4(al, abase + S_XL + ao[ch]);
            mma16816(c1[0], ah[ch], bh[0], bh[1]);
            mma16816(c2[0], ah[ch], bl[0], bl[1]);
            mma16816(c2[0], al,     bh[0], bh[1]);
            mma16816(c1[1], ah[ch], bh[2], bh[3]);
            mma16816(c2[1], ah[ch], bl[2], bl[3]);
            mma16816(c2[1], al,     bh[2], bh[3]);
        }

        #pragma unroll
        for (int s = 0; s < 2; s++) {
            float e[4];
            #pragma unroll
            for (int i = 0; i < 4; i++) {
                float z = c1[s][i] + c2[s][i] * INV2048;
                bool cA = z > m7;
                float b2 = cA ? m11 : m3;
                bool cB = z > b2;
                float b3 = cA ? (cB ? m13 : m9) : (cB ? m5 : m1);
                bool cC = z > b3;
                int e8 = (cA ? 8 : 0) + (cB ? 4 : 0) + (cC ? 2 : 0);
                float b4 = __shfl_sync(0xffffffffu, bndv, e8);
                int idx = e8 + ((z > b4) ? 1 : 0);
                float q = __shfl_sync(0xffffffffu, cbv, idx);
                e[i] = q - z;
            }
            aeAll[ntp][2*s]   = h2u(__floats2half2_rn(e[0], e[1]));
            aeAll[ntp][2*s+1] = h2u(__floats2half2_rn(e[2], e[3]));
        }
    }

    // ==== PHASE 2: GEMM2 per 16-col output block, fused epilogue+store ====
    const int rowA = wid * 16 + g;
    long long grow0 = row0 + rowA;
    long long grow1 = grow0 + 8;
    float scale0 = sScale[rowA];
    float scale1 = sScale[rowA + 8];

    #pragma unroll
    for (int ntp2 = 0; ntp2 < 4; ntp2++) {
        float d[2][4];
        #pragma unroll
        for (int s = 0; s < 2; s++)
            #pragma unroll
            for (int i = 0; i < 4; i++) d[s][i] = 0.f;

        #pragma unroll
        for (int ch = 0; ch < 4; ch++) {
            uint32_t br[4];
            ldsm4(br, sb + S_RT + ntp2 * 2048 + lo[ch]);
            mma16816(d[0], aeAll[ch], br[0], br[1]);
            mma16816(d[1], aeAll[ch], br[2], br[3]);
        }

        // xn back from tiles at the positions matching d slots
        int p0 = 16 * ntp2 + 2 * tq;
        int p1 = p0 + 8;
        __half2 hA = *(const __half2*)(smem + S_XH + sw(rowA, p0));
        __half2 hB = *(const __half2*)(smem + S_XH + sw(rowA, p1));
        __half2 lA = *(const __half2*)(smem + S_XL + sw(rowA, p0));
        __half2 lB = *(const __half2*)(smem + S_XL + sw(rowA, p1));
        float2 fhA = __half22float2(hA), fhB = __half22float2(hB);
        float2 flA = __half22float2(lA), flB = __half22float2(lB);
        if (grow0 < nrows) {
            float4 o;
            o.x = (fhA.x + flA.x * INV2048 + d[0][0]) * scale0;
            o.y = (fhA.y + flA.y * INV2048 + d[0][1]) * scale0;
            o.z = (fhB.x + flB.x * INV2048 + d[1][0]) * scale0;
            o.w = (fhB.y + flB.y * INV2048 + d[1][1]) * scale0;
            *(float4*)(out + grow0 * 64 + 16 * ntp2 + 4 * tq) = o;
        }
        __half2 hC = *(const __half2*)(smem + S_XH + sw(rowA + 8, p0));
        __half2 hD = *(const __half2*)(smem + S_XH + sw(rowA + 8, p1));
        __half2 lC = *(const __half2*)(smem + S_XL + sw(rowA + 8, p0));
        __half2 lD = *(const __half2*)(smem + S_XL + sw(rowA + 8, p1));
        float2 fhC = __half22float2(hC), fhD = __half22float2(hD);
        float2 flC = __half22float2(lC), flD = __half22float2(lD);
        if (grow1 < nrows) {
            float4 o;
            o.x = (fhC.x + flC.x * INV2048 + d[0][2]) * scale1;
            o.y = (fhC.y + flC.y * INV2048 + d[0][3]) * scale1;
            o.z = (fhD.x + flD.x * INV2048 + d[1][2]) * scale1;
            o.w = (fhD.y + flD.y * INV2048 + d[1][3]) * scale1;
            *(float4*)(out + grow1 * 64 + 16 * ntp2 + 4 * tq) = o;
        }
    }
}

extern "C" void kernel_launch(void* const* d_in, const int* in_sizes, int n_in,
                              void* d_out, int out_size)
{
    const float* x  = (const float*)d_in[0];   // [2,32,4096,64] fp32
    const float* cb = (const float*)d_in[1];   // [16] fp32, sorted
    const float* Rg = (const float*)d_in[2];   // [64,64] fp32
    float* out = (float*)d_out;

    int nrows = in_sizes[0] / 64;
    int blocks = (nrows + TILE - 1) / TILE;

    cudaFuncSetAttribute(tq_mma_kernel, cudaFuncAttributeMaxDynamicSharedMemorySize, SMEM_BYTES);
    tq_mma_kernel<<<blocks, NT, SMEM_BYTES>>>(x, cb, Rg, out, nrows);
}

// round 15
// speedup vs baseline: 1.0153x; 1.0153x over previous
#include <cuda_runtime.h>
#include <cuda_fp16.h>
#include <cstdint>

#define TILE 128
#define NT   256

// smem byte offsets. All fp16 tiles: rows of 128 B, SW128 swizzle, identity positions.
#define S_BH    0        // R[j][k] hi        [j][k]      8 KB
#define S_BL    8192     // (R-hi)*2048       [j][k]      8 KB
#define S_RT    16384    // R^T hi            [q(kout)][j] 8 KB (row-permuted for STG.128)
#define S_XH    24576    // xn hi             [128][64]  16 KB
#define S_XL    40960    // xn lo*2048        [128][64]  16 KB
#define S_CB    57344    // float[16]
#define S_BND   57408    // float[15] + pad
#define S_SCALE 57472    // float[128]
#define SMEM_BYTES 57984

#define INV2048 4.8828125e-4f

static __device__ __forceinline__ uint32_t smem_u32(const void* p) {
    uint32_t a;
    asm("{ .reg .u64 t; cvta.to.shared.u64 t, %1; cvt.u32.u64 %0, t; }" : "=r"(a) : "l"(p));
    return a;
}
// byte offset of fp16 element (row, pos) in a [*][64] tile, SW128 swizzle
static __device__ __forceinline__ int sw(int row, int pos) {
    return row * 128 + ((pos * 2) ^ ((row & 7) << 4));
}
// S_RT row permutation: output-col content c sits at tile row q(c) within each 16-block
static __device__ __forceinline__ int qperm(int c) {
    return ((c >> 2) << 1) | (c & 1) | ((c & 2) << 2);
}
static __device__ __forceinline__ uint32_t h2u(__half2 h) {
    return *reinterpret_cast<uint32_t*>(&h);
}
static __device__ __forceinline__ void ldsm4(uint32_t* r, uint32_t addr) {
    asm volatile("ldmatrix.sync.aligned.m8n8.x4.shared.b16 {%0,%1,%2,%3}, [%4];"
        : "=r"(r[0]), "=r"(r[1]), "=r"(r[2]), "=r"(r[3]) : "r"(addr));
}
static __device__ __forceinline__ void mma16816(float* c, const uint32_t* a,
                                                uint32_t b0, uint32_t b1) {
    asm volatile("mma.sync.aligned.m16n8k16.row.col.f32.f16.f16.f32 "
        "{%0,%1,%2,%3}, {%4,%5,%6,%7}, {%8,%9}, {%0,%1,%2,%3};"
        : "+f"(c[0]), "+f"(c[1]), "+f"(c[2]), "+f"(c[3])
        : "r"(a[0]), "r"(a[1]), "r"(a[2]), "r"(a[3]), "r"(b0), "r"(b1));
}

__global__ void __launch_bounds__(NT, 3)
tq_mma_kernel(const float* __restrict__ x, const float* __restrict__ cb,
              const float* __restrict__ Rg, float* __restrict__ out, int nrows)
{
    extern __shared__ char smem[];
    const uint32_t sb = smem_u32(smem);
    float* sCb    = (float*)(smem + S_CB);
    float* sBnd   = (float*)(smem + S_BND);
    float* sScale = (float*)(smem + S_SCALE);

    const int t   = threadIdx.x;
    const int wid = t >> 5;
    const int l   = t & 31;
    const int g   = l >> 2;
    const int tq  = l & 3;
    const long long row0 = (long long)blockIdx.x * TILE;

    // ---- stage R: identity positions for BH/BL; row-permuted S_RT ----
    #pragma unroll 4
    for (int i = t; i < 2048; i += NT) {
        int j = i >> 5, k = (i & 31) * 2;
        float2 vv = *(const float2*)(Rg + j * 64 + k);
        __half2 hv = __floats2half2_rn(vv.x, vv.y);
        float2 hf = __half22float2(hv);
        __half2 lv = __floats2half2_rn((vv.x - hf.x) * 2048.0f, (vv.y - hf.y) * 2048.0f);
        *(__half2*)(smem + S_BH + sw(j, k)) = hv;
        *(__half2*)(smem + S_BL + sw(j, k)) = lv;
        int q0 = (k & ~15) | qperm(k & 15);        // even content -> even-ish row
        int q1 = (k & ~15) | qperm((k & 15) + 1);  // = q0 + 1
        *(__half*)(smem + S_RT + sw(q0, j)) = __low2half(hv);
        *(__half*)(smem + S_RT + sw(q1, j)) = __high2half(hv);
    }
    if (t < 16) sCb[t] = cb[t];
    if (t < 15) sBnd[t] = 0.5f * (cb[t] + cb[t + 1]);

    // ---- prologue: 2 threads/row, coalesced LDG.128; packed STS.128 hi/lo tiles ----
    {
        int r = t >> 1, h = t & 1;
        long long grow = row0 + r;
        long long gr = grow < nrows ? grow : (long long)nrows - 1;
        const float4* xp = (const float4*)(x + gr * 64 + h * 32);
        float4 v[8];
        float ss = 0.f;
        #pragma unroll
        for (int i = 0; i < 8; i++) {
            v[i] = xp[i];
            ss += v[i].x*v[i].x + v[i].y*v[i].y + v[i].z*v[i].z + v[i].w*v[i].w;
        }
        ss += __shfl_xor_sync(0xffffffffu, ss, 1);
        float scale = fmaxf(sqrtf(ss), 1e-8f);
        float inv = 1.0f / scale;
        if (h == 0) sScale[r] = scale;
        const int rswz = (r & 7) << 4;
        #pragma unroll
        for (int p = 0; p < 4; p++) {
            uint32_t uh[4], ul[4];
            #pragma unroll
            for (int q = 0; q < 2; q++) {
                float4 vv = v[2*p + q];
                float a0 = vv.x*inv, a1 = vv.y*inv, a2 = vv.z*inv, a3 = vv.w*inv;
                __half2 hA = __floats2half2_rn(a0, a1);
                __half2 hB = __floats2half2_rn(a2, a3);
                float2 fA = __half22float2(hA), fB = __half22float2(hB);
                uh[2*q]   = h2u(hA);
                uh[2*q+1] = h2u(hB);
                ul[2*q]   = h2u(__floats2half2_rn((a0-fA.x)*2048.0f, (a1-fA.y)*2048.0f));
                ul[2*q+1] = h2u(__floats2half2_rn((a2-fB.x)*2048.0f, (a3-fB.y)*2048.0f));
            }
            int off = r * 128 + (((h << 6) + (p << 4)) ^ rswz);   // 16B-aligned chunk
            *(uint4*)(smem + S_XH + off) = make_uint4(uh[0], uh[1], uh[2], uh[3]);
            *(uint4*)(smem + S_XL + off) = make_uint4(ul[0], ul[1], ul[2], ul[3]);
        }
    }
    __syncthreads();

    // quantizer tables: tree levels 1-3 in regs, level 4 + values via warp shuffle
    const float m1 = sBnd[1], m3 = sBnd[3], m5 = sBnd[5], m7 = sBnd[7];
    const float m9 = sBnd[9], m11 = sBnd[11], m13 = sBnd[13];
    const float bndv = sBnd[l & 15];
    const float cbv  = sCb[l & 15];

    // ---- LDSM lane addressing ----
    const int tl  = l >> 3;
    const int rwi = l & 7;
    const int lswz = rwi << 4;
    // B tiles: b0=(n0-7,k0-7) b1=(n0-7,k8-15) b2=(n8-15,k0-7) b3=(n8-15,k8-15)
    const int rsel = ((tl & 2) << 2) + rwi;
    const int cbyte = (tl & 1) << 4;
    int lo[4];
    #pragma unroll
    for (int ch = 0; ch < 4; ch++) lo[ch] = rsel * 128 + ((ch * 32 + cbyte) ^ lswz);
    // A tiles: a0=(r0-7,p0-7) a1=(r8-15,p0-7) a2=(r0-7,p8-15) a3=(r8-15,p8-15)
    const int arow = wid * 16 + ((tl & 1) << 3) + rwi;
    const int apb  = ((tl >> 1) & 1) << 4;
    int ao[4];
    #pragma unroll
    for (int ch = 0; ch < 4; ch++) ao[ch] = arow * 128 + ((ch * 32 + apb) ^ lswz);

    // hoist A-hi fragments (16 regs)
    uint32_t ah[4][4];
    #pragma unroll
    for (int ch = 0; ch < 4; ch++) ldsm4(ah[ch], sb + S_XH + ao[ch]);

    // ==== PHASE 1: GEMM1 + quantize; E fragments in registers ====
    uint32_t aeAll[4][4];
    #pragma unroll
    for (int ntp = 0; ntp < 4; ntp++) {
        float c1[2][4], c2[2][4];
        #pragma unroll
        for (int s = 0; s < 2; s++)
            #pragma unroll
            for (int i = 0; i < 4; i++) { c1[s][i] = 0.f; c2[s][i] = 0.f; }

        #pragma unroll
        for (int ch = 0; ch < 4; ch++) {
            uint32_t bh[4], bl[4], al[4];
            ldsm4(bh, sb + S_BH + ntp * 2048 + lo[ch]);
            ldsm4(bl, sb + S_BL + ntp * 2048 + lo[ch]);
            ldsm4(al, sb + S_XL + ao[ch]);
            mma16816(c1[0], ah[ch], bh[0], bh[1]);
            mma16816(c2[0], ah[ch], bl[0], bl[1]);
            mma16816(c2[0], al,     bh[0], bh[1]);
            mma16816(c1[1], ah[ch], bh[2], bh[3]);
            mma16816(c2[1], ah[ch], bl[2], bl[3]);
            mma16816(c2[1], al,     bh[2], bh[3]);
        }

        #pragma unroll
        for (int s = 0; s < 2; s++) {
            float e[4];
            #pragma unroll
            for (int i = 0; i < 4; i++) {
                float z = c1[s][i] + c2[s][i] * INV2048;
                bool cA = z > m7;
                float b2 = cA ? m11 : m3;
                bool cB = z > b2;
                float b3 = cA ? (cB ? m13 : m9) : (cB ? m5 : m1);
                bool cC = z > b3;
                int e8 = (cA ? 8 : 0) + (cB ? 4 : 0) + (cC ? 2 : 0);
                float b4 = __shfl_sync(0xffffffffu, bndv, e8);
                int idx = e8 + ((z > b4) ? 1 : 0);
                float q = __shfl_sync(0xffffffffu, cbv, idx);
                e[i] = q - z;
            }
            aeAll[ntp][2*s]   = h2u(__floats2half2_rn(e[0], e[1]));
            aeAll[ntp][2*s+1] = h2u(__floats2half2_rn(e[2], e[3]));
        }
    }

    // ==== PHASE 2: GEMM2 per 16-col output block, fused epilogue+store ====
    const int rowA = wid * 16 + g;
    long long grow0 = row0 + rowA;
    long long grow1 = grow0 + 8;
    float scale0 = sScale[rowA];
    float scale1 = sScale[rowA + 8];
    const int esz0 = (rowA & 7) << 4;
    const int esz1 = ((rowA + 8) & 7) << 4;

    #pragma unroll
    for (int ntp2 = 0; ntp2 < 4; ntp2++) {
        float d[2][4];
        #pragma unroll
        for (int s = 0; s < 2; s++)
            #pragma unroll
            for (int i = 0; i < 4; i++) d[s][i] = 0.f;

        #pragma unroll
        for (int ch = 0; ch < 4; ch++) {
            uint32_t br[4];
            ldsm4(br, sb + S_RT + ntp2 * 2048 + lo[ch]);
            mma16816(d[0], aeAll[ch], br[0], br[1]);
            mma16816(d[1], aeAll[ch], br[2], br[3]);
        }

        // xn back from tiles (identity positions): contents 16ntp2+4tq..+3
        int cb0 = (32 * ntp2 + 8 * tq);
        if (grow0 < nrows) {
            uint2 uh = *(const uint2*)(smem + S_XH + rowA * 128 + (cb0 ^ esz0));
            uint2 ulw = *(const uint2*)(smem + S_XL + rowA * 128 + (cb0 ^ esz0));
            float2 hA = __half22float2(*reinterpret_cast<__half2*>(&uh.x));
            float2 hB = __half22float2(*reinterpret_cast<__half2*>(&uh.y));
            float2 lA = __half22float2(*reinterpret_cast<__half2*>(&ulw.x));
            float2 lB = __half22float2(*reinterpret_cast<__half2*>(&ulw.y));
            float4 o;
            o.x = (hA.x + lA.x * INV2048 + d[0][0]) * scale0;
            o.y = (hA.y + lA.y * INV2048 + d[0][1]) * scale0;
            o.z = (hB.x + lB.x * INV2048 + d[1][0]) * scale0;
            o.w = (hB.y + lB.y * INV2048 + d[1][1]) * scale0;
            *(float4*)(out + grow0 * 64 + 16 * ntp2 + 4 * tq) = o;
        }
        if (grow1 < nrows) {
            uint2 uh = *(const uint2*)(smem + S_XH + (rowA + 8) * 128 + (cb0 ^ esz1));
            uint2 ulw = *(const uint2*)(smem + S_XL + (rowA + 8) * 128 + (cb0 ^ esz1));
            float2 hC = __half22float2(*reinterpret_cast<__half2*>(&uh.x));
            float2 hD = __half22float2(*reinterpret_cast<__half2*>(&uh.y));
            float2 lC = __half22float2(*reinterpret_cast<__half2*>(&ulw.x));
            float2 lD = __half22float2(*reinterpret_cast<__half2*>(&ulw.y));
            float4 o;
            o.x = (hC.x + lC.x * INV2048 + d[0][2]) * scale1;
            o.y = (hC.y + lC.y * INV2048 + d[0][3]) * scale1;
            o.z = (hD.x + lD.x * INV2048 + d[1][2]) * scale1;
            o.w = (hD.y + lD.y * INV2048 + d[1][3]) * scale1;
            *(float4*)(out + grow1 * 64 + 16 * ntp2 + 4 * tq) = o;
        }
    }
}

extern "C" void kernel_launch(void* const* d_in, const int* in_sizes, int n_in,
                              void* d_out, int out_size)
{
    const float* x  = (const float*)d_in[0];   // [2,32,4096,64] fp32
    const float* cb = (const float*)d_in[1];   // [16] fp32, sorted
    const float* Rg = (const float*)d_in[2];   // [64,64] fp32
    float* out = (float*)d_out;

    int nrows = in_sizes[0] / 64;
    int blocks = (nrows + TILE - 1) / TILE;

    cudaFuncSetAttribute(tq_mma_kernel, cudaFuncAttributeMaxDynamicSharedMemorySize, SMEM_BYTES);
    tq_mma_kernel<<<blocks, NT, SMEM_BYTES>>>(x, cb, Rg, out, nrows);
}

// round 16
// speedup vs baseline: 1.3857x; 1.3649x over previous
#include <cuda_runtime.h>
#include <cuda_fp16.h>
#include <cstdint>

#define TILE 128
#define NT   256

// smem byte offsets. B tiles: 64 rows x 128 B, SW128 swizzle.
#define S_BH   0        // GEMM1 B hi (k-cols permuted)
#define S_BL   8192     // GEMM1 B lo*2048 (k-cols permuted)
#define S_RT   16384    // GEMM2 B = R^T hi (n-rows permuted)
#define S_CB   24576    // float[16]
#define S_BND  24640    // float[15] + pad
#define SMEM_BYTES 24704

#define INV2048 4.8828125e-4f

static __device__ __forceinline__ uint32_t smem_u32(const void* p) {
    uint32_t a;
    asm("{ .reg .u64 t; cvta.to.shared.u64 t, %1; cvt.u32.u64 %0, t; }" : "=r"(a) : "l"(p));
    return a;
}
// byte offset of fp16 (row, col) in a [*][64] fp16 tile with SW128 swizzle
static __device__ __forceinline__ int sw(int row, int col) {
    return row * 128 + ((col * 2) ^ ((row & 7) << 4));
}
// inverse of the fragment k-permutation
static __device__ __forceinline__ int invperm(int s) {
    return ((s >> 2) << 1) | (s & 1) | ((s & 2) << 2);
}
static __device__ __forceinline__ uint32_t h2u(__half2 h) {
    return *reinterpret_cast<uint32_t*>(&h);
}
static __device__ __forceinline__ void ldsm4(uint32_t* r, uint32_t addr) {
    asm volatile("ldmatrix.sync.aligned.m8n8.x4.shared.b16 {%0,%1,%2,%3}, [%4];"
        : "=r"(r[0]), "=r"(r[1]), "=r"(r[2]), "=r"(r[3]) : "r"(addr));
}
static __device__ __forceinline__ void mma16816(float* c, const uint32_t* a,
                                                uint32_t b0, uint32_t b1) {
    asm volatile("mma.sync.aligned.m16n8k16.row.col.f32.f16.f16.f32 "
        "{%0,%1,%2,%3}, {%4,%5,%6,%7}, {%8,%9}, {%0,%1,%2,%3};"
        : "+f"(c[0]), "+f"(c[1]), "+f"(c[2]), "+f"(c[3])
        : "r"(a[0]), "r"(a[1]), "r"(a[2]), "r"(a[3]), "r"(b0), "r"(b1));
}

__global__ void __launch_bounds__(NT, 2)
tq_mma_kernel(const float* __restrict__ x, const float* __restrict__ cb,
              const float* __restrict__ Rg, float* __restrict__ out, int nrows)
{
    extern __shared__ char smem[];
    const uint32_t sb = smem_u32(smem);
    float* sCb  = (float*)(smem + S_CB);
    float* sBnd = (float*)(smem + S_BND);

    const int t   = threadIdx.x;
    const int wid = t >> 5;
    const int l   = t & 31;
    const int g   = l >> 2;      // fragment row group 0..7
    const int tq  = l & 3;       // fragment quad col
    const long long row0 = (long long)blockIdx.x * TILE;

    // ---- stage R with the fragment k-permutation baked in ----
    #pragma unroll 4
    for (int i = t; i < 4096; i += NT) {
        int j = i >> 6, k = i & 63;
        float v = Rg[i];
        __half hv = __float2half_rn(v);
        __half lv = __float2half_rn((v - __half2float(hv)) * 2048.0f);
        int kk = (k & ~15) | invperm(k & 15);
        *(__half*)(smem + S_BH + sw(j, kk)) = hv;    // GEMM1: n=j, k-col permuted
        *(__half*)(smem + S_BL + sw(j, kk)) = lv;
        *(__half*)(smem + S_RT + sw(kk, j)) = hv;    // GEMM2: n-row permuted, k-col=j
    }
    if (t < 16) sCb[t] = cb[t];
    if (t < 15) sBnd[t] = 0.5f * (cb[t] + cb[t + 1]);

    // ---- load x as float4s: rows rowA/rowA+8, cols 16ch+4tq..+3 ----
    const int rowA = wid * 16 + g;
    long long grow0 = row0 + rowA;
    long long grow1 = grow0 + 8;
    long long gr0 = grow0 < nrows ? grow0 : (long long)nrows - 1;
    long long gr1 = grow1 < nrows ? grow1 : (long long)nrows - 1;

    float4 v0[4], v1[4];
    float ss0 = 0.f, ss1 = 0.f;
    #pragma unroll
    for (int ch = 0; ch < 4; ch++) {
        v0[ch] = *(const float4*)(x + gr0 * 64 + 16 * ch + 4 * tq);
        v1[ch] = *(const float4*)(x + gr1 * 64 + 16 * ch + 4 * tq);
        ss0 += v0[ch].x*v0[ch].x + v0[ch].y*v0[ch].y + v0[ch].z*v0[ch].z + v0[ch].w*v0[ch].w;
        ss1 += v1[ch].x*v1[ch].x + v1[ch].y*v1[ch].y + v1[ch].z*v1[ch].z + v1[ch].w*v1[ch].w;
    }
    ss0 += __shfl_xor_sync(0xffffffffu, ss0, 1);
    ss0 += __shfl_xor_sync(0xffffffffu, ss0, 2);
    ss1 += __shfl_xor_sync(0xffffffffu, ss1, 1);
    ss1 += __shfl_xor_sync(0xffffffffu, ss1, 2);
    float scale0 = fmaxf(sqrtf(ss0), 1e-8f);
    float scale1 = fmaxf(sqrtf(ss1), 1e-8f);
    float inv0 = 1.0f / scale0;
    float inv1 = 1.0f / scale1;

    // split hi / scaled-lo; xh0[2ch]=cols(+0,+1) row g, xh0[2ch+1]=cols(+2,+3)
    uint32_t xh0[8], xl0[8], xh1[8], xl1[8];
    #pragma unroll
    for (int ch = 0; ch < 4; ch++) {
        float a0 = v0[ch].x*inv0, a1 = v0[ch].y*inv0, a2 = v0[ch].z*inv0, a3 = v0[ch].w*inv0;
        float b0 = v1[ch].x*inv1, b1 = v1[ch].y*inv1, b2 = v1[ch].z*inv1, b3 = v1[ch].w*inv1;
        __half2 hA = __floats2half2_rn(a0, a1), hB = __floats2half2_rn(a2, a3);
        __half2 hC = __floats2half2_rn(b0, b1), hD = __floats2half2_rn(b2, b3);
        float2 fA = __half22float2(hA), fB = __half22float2(hB);
        float2 fC = __half22float2(hC), fD = __half22float2(hD);
        xh0[2*ch]   = h2u(hA); xh0[2*ch+1] = h2u(hB);
        xh1[2*ch]   = h2u(hC); xh1[2*ch+1] = h2u(hD);
        xl0[2*ch]   = h2u(__floats2half2_rn((a0-fA.x)*2048.0f, (a1-fA.y)*2048.0f));
        xl0[2*ch+1] = h2u(__floats2half2_rn((a2-fB.x)*2048.0f, (a3-fB.y)*2048.0f));
        xl1[2*ch]   = h2u(__floats2half2_rn((b0-fC.x)*2048.0f, (b1-fC.y)*2048.0f));
        xl1[2*ch+1] = h2u(__floats2half2_rn((b2-fD.x)*2048.0f, (b3-fD.y)*2048.0f));
    }
    __syncthreads();   // B tiles + tables ready

    // quantizer tables: tree levels 1-3 in regs, level 4 + values via warp shuffle
    const float m1 = sBnd[1], m3 = sBnd[3], m5 = sBnd[5], m7 = sBnd[7];
    const float m9 = sBnd[9], m11 = sBnd[11], m13 = sBnd[13];
    const float bndv = sBnd[l & 15];
    const float cbv  = sCb[l & 15];

    // ---- LDSM lane addressing (shared by all three B tiles) ----
    const int tl  = l >> 3;
    const int rwi = l & 7;
    const int rsel = ((tl & 2) << 2) + rwi;
    const int cbyte = (tl & 1) << 4;
    const int swz = rwi << 4;
    int lo[4];
    #pragma unroll
    for (int ch = 0; ch < 4; ch++) lo[ch] = rsel * 128 + ((ch * 32 + cbyte) ^ swz);

    // ==== PHASE 1: GEMM1 + quantize; all E fragments kept in registers ====
    uint32_t aeAll[4][4];
    #pragma unroll
    for (int ntp = 0; ntp < 4; ntp++) {
        float c1[2][4], c2[2][4];
        #pragma unroll
        for (int s = 0; s < 2; s++)
            #pragma unroll
            for (int i = 0; i < 4; i++) { c1[s][i] = 0.f; c2[s][i] = 0.f; }

        #pragma unroll
        for (int ch = 0; ch < 4; ch++) {
            uint32_t bh[4], bl[4];
            ldsm4(bh, sb + S_BH + ntp * 2048 + lo[ch]);
            ldsm4(bl, sb + S_BL + ntp * 2048 + lo[ch]);
            uint32_t ah[4] = { xh0[2*ch], xh1[2*ch], xh0[2*ch+1], xh1[2*ch+1] };
            uint32_t al[4] = { xl0[2*ch], xl1[2*ch], xl0[2*ch+1], xl1[2*ch+1] };
            mma16816(c1[0], ah, bh[0], bh[1]);
            mma16816(c2[0], ah, bl[0], bl[1]);
            mma16816(c2[0], al, bh[0], bh[1]);
            mma16816(c1[1], ah, bh[2], bh[3]);
            mma16816(c2[1], ah, bl[2], bl[3]);
            mma16816(c2[1], al, bh[2], bh[3]);
        }

        #pragma unroll
        for (int s = 0; s < 2; s++) {
            float e[4];
            #pragma unroll
            for (int i = 0; i < 4; i++) {
                float z = c1[s][i] + c2[s][i] * INV2048;
                bool cA = z > m7;
                float b2 = cA ? m11 : m3;
                bool cB = z > b2;
                float b3 = cA ? (cB ? m13 : m9) : (cB ? m5 : m1);
                bool cC = z > b3;
                int e8 = (cA ? 8 : 0) + (cB ? 4 : 0) + (cC ? 2 : 0);
                float b4 = __shfl_sync(0xffffffffu, bndv, e8);
                int idx = e8 + ((z > b4) ? 1 : 0);
                float q = __shfl_sync(0xffffffffu, cbv, idx);
                e[i] = q - z;
            }
            aeAll[ntp][2*s]   = h2u(__floats2half2_rn(e[0], e[1]));
            aeAll[ntp][2*s+1] = h2u(__floats2half2_rn(e[2], e[3]));
        }
    }

    // ==== PHASE 2: GEMM2 per 16-col output block, fused epilogue+store ====
    #pragma unroll
    for (int ntp2 = 0; ntp2 < 4; ntp2++) {
        float d[2][4];
        #pragma unroll
        for (int s = 0; s < 2; s++)
            #pragma unroll
            for (int i = 0; i < 4; i++) d[s][i] = 0.f;

        #pragma unroll
        for (int ch = 0; ch < 4; ch++) {
            uint32_t br[4];
            ldsm4(br, sb + S_RT + ntp2 * 2048 + lo[ch]);
            mma16816(d[0], aeAll[ch], br[0], br[1]);
            mma16816(d[1], aeAll[ch], br[2], br[3]);
        }

        // y = xn + E@R (cols re-aligned by the permutation), rescale, store
        float2 hA = __half22float2(*reinterpret_cast<__half2*>(&xh0[2*ntp2]));
        float2 lA = __half22float2(*reinterpret_cast<__half2*>(&xl0[2*ntp2]));
        float2 hB = __half22float2(*reinterpret_cast<__half2*>(&xh0[2*ntp2+1]));
        float2 lB = __half22float2(*reinterpret_cast<__half2*>(&xl0[2*ntp2+1]));
        if (grow0 < nrows) {
            float4 o;
            o.x = (hA.x + lA.x * INV2048 + d[0][0]) * scale0;
            o.y = (hA.y + lA.y * INV2048 + d[0][1]) * scale0;
            o.z = (hB.x + lB.x * INV2048 + d[1][0]) * scale0;
            o.w = (hB.y + lB.y * INV2048 + d[1][1]) * scale0;
            *(float4*)(out + grow0 * 64 + 16 * ntp2 + 4 * tq) = o;
        }
        float2 hC = __half22float2(*reinterpret_cast<__half2*>(&xh1[2*ntp2]));
        float2 lC = __half22float2(*reinterpret_cast<__half2*>(&xl1[2*ntp2]));
        float2 hD = __half22float2(*reinterpret_cast<__half2*>(&xh1[2*ntp2+1]));
        float2 lD = __half22float2(*reinterpret_cast<__half2*>(&xl1[2*ntp2+1]));
        if (grow1 < nrows) {
            float4 o;
            o.x = (hC.x + lC.x * INV2048 + d[0][2]) * scale1;
            o.y = (hC.y + lC.y * INV2048 + d[0][3]) * scale1;
            o.z = (hD.x + lD.x * INV2048 + d[1][2]) * scale1;
            o.w = (hD.y + lD.y * INV2048 + d[1][3]) * scale1;
            *(float4*)(out + grow1 * 64 + 16 * ntp2 + 4 * tq) = o;
        }
    }
}

extern "C" void kernel_launch(void* const* d_in, const int* in_sizes, int n_in,
                              void* d_out, int out_size)
{
    const float* x  = (const float*)d_in[0];   // [2,32,4096,64] fp32
    const float* cb = (const float*)d_in[1];   // [16] fp32, sorted
    const float* Rg = (const float*)d_in[2];   // [64,64] fp32
    float* out = (float*)d_out;

    int nrows = in_sizes[0] / 64;
    int blocks = (nrows + TILE - 1) / TILE;

    tq_mma_kernel<<<blocks, NT, SMEM_BYTES>>>(x, cb, Rg, out, nrows);
}

// round 17
// speedup vs baseline: 1.5000x; 1.0825x over previous
#include <cuda_runtime.h>
#include <cuda_fp16.h>
#include <cstdint>

#define TILE 256
#define NT   256

// smem byte offsets. B tiles: 64 rows x 128 B, SW128 swizzle.
#define S_BH   0        // GEMM1 B hi (k-cols permuted)
#define S_BL   8192     // GEMM1 B lo*2048 (k-cols permuted)
#define S_RT   16384    // GEMM2 B = R^T hi (n-rows permuted)
#define S_CB   24576    // float[16]
#define S_BND  24640    // float[15] + pad
#define SMEM_BYTES 24704

#define INV2048 4.8828125e-4f

static __device__ __forceinline__ uint32_t smem_u32(const void* p) {
    uint32_t a;
    asm("{ .reg .u64 t; cvta.to.shared.u64 t, %1; cvt.u32.u64 %0, t; }" : "=r"(a) : "l"(p));
    return a;
}
// byte offset of fp16 (row, col) in a [*][64] fp16 tile with SW128 swizzle
static __device__ __forceinline__ int sw(int row, int col) {
    return row * 128 + ((col * 2) ^ ((row & 7) << 4));
}
// inverse of the fragment k-permutation (maps even k to even slot; k,k+1 stay adjacent)
static __device__ __forceinline__ int invperm(int s) {
    return ((s >> 2) << 1) | (s & 1) | ((s & 2) << 2);
}
static __device__ __forceinline__ uint32_t h2u(__half2 h) {
    return *reinterpret_cast<uint32_t*>(&h);
}
static __device__ __forceinline__ void ldsm4(uint32_t* r, uint32_t addr) {
    asm volatile("ldmatrix.sync.aligned.m8n8.x4.shared.b16 {%0,%1,%2,%3}, [%4];"
        : "=r"(r[0]), "=r"(r[1]), "=r"(r[2]), "=r"(r[3]) : "r"(addr));
}
static __device__ __forceinline__ void mma16816(float* c, const uint32_t* a,
                                                uint32_t b0, uint32_t b1) {
    asm volatile("mma.sync.aligned.m16n8k16.row.col.f32.f16.f16.f32 "
        "{%0,%1,%2,%3}, {%4,%5,%6,%7}, {%8,%9}, {%0,%1,%2,%3};"
        : "+f"(c[0]), "+f"(c[1]), "+f"(c[2]), "+f"(c[3])
        : "r"(a[0]), "r"(a[1]), "r"(a[2]), "r"(a[3]), "r"(b0), "r"(b1));
}

__global__ void __launch_bounds__(NT, 2)
tq_mma_kernel(const float* __restrict__ x, const float* __restrict__ cb,
              const float* __restrict__ Rg, float* __restrict__ out, int nrows)
{
    extern __shared__ char smem[];
    const uint32_t sb = smem_u32(smem);
    float* sCb  = (float*)(smem + S_CB);
    float* sBnd = (float*)(smem + S_BND);

    const int t   = threadIdx.x;
    const int wid = t >> 5;
    const int l   = t & 31;
    const int g   = l >> 2;      // fragment row group 0..7
    const int tq  = l & 3;       // fragment quad col
    const long long row0 = (long long)blockIdx.x * TILE;

    // ---- stage R (half2 pairs; fragment k-permutation baked in) ----
    #pragma unroll 4
    for (int i = t; i < 2048; i += NT) {
        int j = i >> 5, k = (i & 31) * 2;
        float2 vv = *(const float2*)(Rg + j * 64 + k);
        __half2 hv = __floats2half2_rn(vv.x, vv.y);
        float2 hf = __half22float2(hv);
        __half2 lv = __floats2half2_rn((vv.x - hf.x) * 2048.0f, (vv.y - hf.y) * 2048.0f);
        int kk = (k & ~15) | invperm(k & 15);   // even; pair stays adjacent
        *(__half2*)(smem + S_BH + sw(j, kk)) = hv;
        *(__half2*)(smem + S_BL + sw(j, kk)) = lv;
        *(__half*)(smem + S_RT + sw(kk,     j)) = __low2half(hv);
        *(__half*)(smem + S_RT + sw(kk + 1, j)) = __high2half(hv);
    }
    if (t < 16) sCb[t] = cb[t];
    if (t < 15) sBnd[t] = 0.5f * (cb[t] + cb[t + 1]);
    __syncthreads();   // B tiles + tables ready

    // quantizer tables: tree levels 1-3 in regs, level 4 + values via warp shuffle
    const float m1 = sBnd[1], m3 = sBnd[3], m5 = sBnd[5], m7 = sBnd[7];
    const float m9 = sBnd[9], m11 = sBnd[11], m13 = sBnd[13];
    const float bndv = sBnd[l & 15];
    const float cbv  = sCb[l & 15];

    // ---- LDSM lane addressing (shared by all three B tiles) ----
    const int tl  = l >> 3;
    const int rwi = l & 7;
    const int rsel = ((tl & 2) << 2) + rwi;
    const int cbyte = (tl & 1) << 4;
    const int swz = rwi << 4;
    int lo[4];
    #pragma unroll
    for (int ch = 0; ch < 4; ch++) lo[ch] = rsel * 128 + ((ch * 32 + cbyte) ^ swz);

    // ==== process two 128-row halves sequentially (B tiles reused) ====
    #pragma unroll 1
    for (int half = 0; half < 2; ++half) {
        const int rowA = half * 128 + wid * 16 + g;
        long long grow0 = row0 + rowA;
        long long grow1 = grow0 + 8;
        long long gr0 = grow0 < nrows ? grow0 : (long long)nrows - 1;
        long long gr1 = grow1 < nrows ? grow1 : (long long)nrows - 1;

        // ---- load x as float4s: rows grow0/grow1, cols 16ch+4tq..+3 ----
        float4 v0[4], v1[4];
        float ss0 = 0.f, ss1 = 0.f;
        #pragma unroll
        for (int ch = 0; ch < 4; ch++) {
            v0[ch] = *(const float4*)(x + gr0 * 64 + 16 * ch + 4 * tq);
            v1[ch] = *(const float4*)(x + gr1 * 64 + 16 * ch + 4 * tq);
            ss0 += v0[ch].x*v0[ch].x + v0[ch].y*v0[ch].y + v0[ch].z*v0[ch].z + v0[ch].w*v0[ch].w;
            ss1 += v1[ch].x*v1[ch].x + v1[ch].y*v1[ch].y + v1[ch].z*v1[ch].z + v1[ch].w*v1[ch].w;
        }
        ss0 += __shfl_xor_sync(0xffffffffu, ss0, 1);
        ss0 += __shfl_xor_sync(0xffffffffu, ss0, 2);
        ss1 += __shfl_xor_sync(0xffffffffu, ss1, 1);
        ss1 += __shfl_xor_sync(0xffffffffu, ss1, 2);
        float scale0 = fmaxf(sqrtf(ss0), 1e-8f);
        float scale1 = fmaxf(sqrtf(ss1), 1e-8f);
        float inv0 = 1.0f / scale0;
        float inv1 = 1.0f / scale1;

        // split hi / scaled-lo into fragment registers
        uint32_t xh0[8], xl0[8], xh1[8], xl1[8];
        #pragma unroll
        for (int ch = 0; ch < 4; ch++) {
            float a0 = v0[ch].x*inv0, a1 = v0[ch].y*inv0, a2 = v0[ch].z*inv0, a3 = v0[ch].w*inv0;
            float b0 = v1[ch].x*inv1, b1 = v1[ch].y*inv1, b2 = v1[ch].z*inv1, b3 = v1[ch].w*inv1;
            __half2 hA = __floats2half2_rn(a0, a1), hB = __floats2half2_rn(a2, a3);
            __half2 hC = __floats2half2_rn(b0, b1), hD = __floats2half2_rn(b2, b3);
            float2 fA = __half22float2(hA), fB = __half22float2(hB);
            float2 fC = __half22float2(hC), fD = __half22float2(hD);
            xh0[2*ch]   = h2u(hA); xh0[2*ch+1] = h2u(hB);
            xh1[2*ch]   = h2u(hC); xh1[2*ch+1] = h2u(hD);
            xl0[2*ch]   = h2u(__floats2half2_rn((a0-fA.x)*2048.0f, (a1-fA.y)*2048.0f));
            xl0[2*ch+1] = h2u(__floats2half2_rn((a2-fB.x)*2048.0f, (a3-fB.y)*2048.0f));
            xl1[2*ch]   = h2u(__floats2half2_rn((b0-fC.x)*2048.0f, (b1-fC.y)*2048.0f));
            xl1[2*ch+1] = h2u(__floats2half2_rn((b2-fD.x)*2048.0f, (b3-fD.y)*2048.0f));
        }

        // ==== PHASE 1: GEMM1 + quantize; all E fragments kept in registers ====
        uint32_t aeAll[4][4];
        #pragma unroll
        for (int ntp = 0; ntp < 4; ntp++) {
            float c1[2][4], c2[2][4];
            #pragma unroll
            for (int s = 0; s < 2; s++)
                #pragma unroll
                for (int i = 0; i < 4; i++) { c1[s][i] = 0.f; c2[s][i] = 0.f; }

            #pragma unroll
            for (int ch = 0; ch < 4; ch++) {
                uint32_t bh[4], bl[4];
                ldsm4(bh, sb + S_BH + ntp * 2048 + lo[ch]);
                ldsm4(bl, sb + S_BL + ntp * 2048 + lo[ch]);
                uint32_t ah[4] = { xh0[2*ch], xh1[2*ch], xh0[2*ch+1], xh1[2*ch+1] };
                uint32_t al[4] = { xl0[2*ch], xl1[2*ch], xl0[2*ch+1], xl1[2*ch+1] };
                mma16816(c1[0], ah, bh[0], bh[1]);
                mma16816(c2[0], ah, bl[0], bl[1]);
                mma16816(c2[0], al, bh[0], bh[1]);
                mma16816(c1[1], ah, bh[2], bh[3]);
                mma16816(c2[1], ah, bl[2], bl[3]);
                mma16816(c2[1], al, bh[2], bh[3]);
            }

            #pragma unroll
            for (int s = 0; s < 2; s++) {
                float e[4];
                #pragma unroll
                for (int i = 0; i < 4; i++) {
                    float z = c1[s][i] + c2[s][i] * INV2048;
                    bool cA = z > m7;
                    float b2 = cA ? m11 : m3;
                    bool cB = z > b2;
                    float b3 = cA ? (cB ? m13 : m9) : (cB ? m5 : m1);
                    bool cC = z > b3;
                    int e8 = (cA ? 8 : 0) + (cB ? 4 : 0) + (cC ? 2 : 0);
                    float b4 = __shfl_sync(0xffffffffu, bndv, e8);
                    int idx = e8 + ((z > b4) ? 1 : 0);
                    float q = __shfl_sync(0xffffffffu, cbv, idx);
                    e[i] = q - z;
                }
                aeAll[ntp][2*s]   = h2u(__floats2half2_rn(e[0], e[1]));
                aeAll[ntp][2*s+1] = h2u(__floats2half2_rn(e[2], e[3]));
            }
        }

        // ==== PHASE 2: GEMM2 per 16-col output block, fused epilogue+store ====
        #pragma unroll
        for (int ntp2 = 0; ntp2 < 4; ntp2++) {
            float d[2][4];
            #pragma unroll
            for (int s = 0; s < 2; s++)
                #pragma unroll
                for (int i = 0; i < 4; i++) d[s][i] = 0.f;

            #pragma unroll
            for (int ch = 0; ch < 4; ch++) {
                uint32_t br[4];
                ldsm4(br, sb + S_RT + ntp2 * 2048 + lo[ch]);
                mma16816(d[0], aeAll[ch], br[0], br[1]);
                mma16816(d[1], aeAll[ch], br[2], br[3]);
            }

            // y = xn + E@R (cols re-aligned by the permutation), rescale, store
            float2 hA = __half22float2(*reinterpret_cast<__half2*>(&xh0[2*ntp2]));
            float2 lA = __half22float2(*reinterpret_cast<__half2*>(&xl0[2*ntp2]));
            float2 hB = __half22float2(*reinterpret_cast<__half2*>(&xh0[2*ntp2+1]));
            float2 lB = __half22float2(*reinterpret_cast<__half2*>(&xl0[2*ntp2+1]));
            if (grow0 < nrows) {
                float4 o;
                o.x = (hA.x + lA.x * INV2048 + d[0][0]) * scale0;
                o.y = (hA.y + lA.y * INV2048 + d[0][1]) * scale0;
                o.z = (hB.x + lB.x * INV2048 + d[1][0]) * scale0;
                o.w = (hB.y + lB.y * INV2048 + d[1][1]) * scale0;
                *(float4*)(out + grow0 * 64 + 16 * ntp2 + 4 * tq) = o;
            }
            float2 hC = __half22float2(*reinterpret_cast<__half2*>(&xh1[2*ntp2]));
            float2 lC = __half22float2(*reinterpret_cast<__half2*>(&xl1[2*ntp2]));
            float2 hD = __half22float2(*reinterpret_cast<__half2*>(&xh1[2*ntp2+1]));
            float2 lD = __half22float2(*reinterpret_cast<__half2*>(&xl1[2*ntp2+1]));
            if (grow1 < nrows) {
                float4 o;
                o.x = (hC.x + lC.x * INV2048 + d[0][2]) * scale1;
                o.y = (hC.y + lC.y * INV2048 + d[0][3]) * scale1;
                o.z = (hD.x + lD.x * INV2048 + d[1][2]) * scale1;
                o.w = (hD.y + lD.y * INV2048 + d[1][3]) * scale1;
                *(float4*)(out + grow1 * 64 + 16 * ntp2 + 4 * tq) = o;
            }
        }
    }
}

extern "C" void kernel_launch(void* const* d_in, const int* in_sizes, int n_in,
                              void* d_out, int out_size)
{
    const float* x  = (const float*)d_in[0];   // [2,32,4096,64] fp32
    const float* cb = (const float*)d_in[1];   // [16] fp32, sorted
    const float* Rg = (const float*)d_in[2];   // [64,64] fp32
    float* out = (float*)d_out;

    int nrows = in_sizes[0] / 64;
    int blocks = (nrows + TILE - 1) / TILE;

    tq_mma_kernel<<<blocks, NT, SMEM_BYTES>>>(x, cb, Rg, out, nrows);
}